// round 13
// baseline (speedup 1.0000x reference)
#include <cuda_runtime.h>
#include <cuda_bf16.h>
#include <math.h>
#include <stdint.h>

// Problem constants
#define NB 8
#define NC 512
#define NT 2048
#define N3C 1536
#define TEMP_INV (1.0f / 0.07f)
#define L2EPS 1e-12f

// ---------------------------------------------------------------------------
// Static scratch (no allocation allowed anywhere)
// ---------------------------------------------------------------------------
__device__ float g_qkv   [(size_t)NB * N3C * NT];
__device__ float g_scores[(size_t)NB * NT  * NT];

__device__ __nv_bfloat16 g_wq_h[(size_t)N3C * NC], g_wq_l[(size_t)N3C * NC];
__device__ __nv_bfloat16 g_wp_h[(size_t)NC  * NC], g_wp_l[(size_t)NC  * NC];
__device__ __nv_bfloat16 g_xT_h[(size_t)NB * NT * NC], g_xT_l[(size_t)NB * NT * NC];
__device__ __nv_bfloat16 g_qT_h[(size_t)NB * NT * NC], g_qT_l[(size_t)NB * NT * NC];
__device__ __nv_bfloat16 g_kT_h[(size_t)NB * NT * NC], g_kT_l[(size_t)NB * NT * NC];
__device__ __nv_bfloat16 g_v_h [(size_t)NB * NC * NT], g_v_l [(size_t)NB * NC * NT];
__device__ __nv_bfloat16 g_at_h[(size_t)NB * NT * NT], g_at_l[(size_t)NB * NT * NT];
__device__ __nv_bfloat16 g_oT_h[(size_t)NB * NT * NC], g_oT_l[(size_t)NB * NT * NC];

// ---------------------------------------------------------------------------
// PTX helpers (baseline sm_80+ only)
// ---------------------------------------------------------------------------
__device__ __forceinline__ uint32_t s2u(const void* p) {
    uint32_t a;
    asm("{ .reg .u64 t; cvta.to.shared.u64 t, %1; cvt.u32.u64 %0, t; }"
        : "=r"(a) : "l"(p));
    return a;
}

__device__ __forceinline__ void cp16(uint32_t s, const void* g) {
    asm volatile("cp.async.cg.shared.global [%0], [%1], 16;" :: "r"(s), "l"(g));
}
#define CP_COMMIT() asm volatile("cp.async.commit_group;" ::: "memory")
#define CP_WAIT(n)  asm volatile("cp.async.wait_group %0;" :: "n"(n) : "memory")

__device__ __forceinline__ void ldsm4(uint32_t* r, uint32_t a) {
    asm volatile("ldmatrix.sync.aligned.m8n8.x4.shared.b16 {%0,%1,%2,%3}, [%4];"
                 : "=r"(r[0]), "=r"(r[1]), "=r"(r[2]), "=r"(r[3]) : "r"(a));
}

// NOTE: non-volatile on purpose — pure register op, lets ptxas schedule.
__device__ __forceinline__ void mma16816(float* c, const uint32_t* a, const uint32_t* b) {
    asm("mma.sync.aligned.m16n8k16.row.col.f32.bf16.bf16.f32 "
        "{%0,%1,%2,%3}, {%4,%5,%6,%7}, {%8,%9}, {%0,%1,%2,%3};"
        : "+f"(c[0]), "+f"(c[1]), "+f"(c[2]), "+f"(c[3])
        : "r"(a[0]), "r"(a[1]), "r"(a[2]), "r"(a[3]), "r"(b[0]), "r"(b[1]));
}

// 128-byte-row XOR swizzle
__device__ __forceinline__ uint32_t swz(uint32_t b) {
    return b ^ (((b >> 7) & 7) << 4);
}

__device__ __forceinline__ void split4(const float* v, uint2& hi, uint2& lo) {
    __nv_bfloat16 h0 = __float2bfloat16(v[0]);
    __nv_bfloat16 h1 = __float2bfloat16(v[1]);
    __nv_bfloat16 h2 = __float2bfloat16(v[2]);
    __nv_bfloat16 h3 = __float2bfloat16(v[3]);
    __nv_bfloat162 a = __nv_bfloat162(h0, h1), b = __nv_bfloat162(h2, h3);
    hi.x = *(uint32_t*)&a;  hi.y = *(uint32_t*)&b;
    __nv_bfloat162 c = __nv_bfloat162(__float2bfloat16(v[0] - __bfloat162float(h0)),
                                      __float2bfloat16(v[1] - __bfloat162float(h1)));
    __nv_bfloat162 d = __nv_bfloat162(__float2bfloat16(v[2] - __bfloat162float(h2)),
                                      __float2bfloat16(v[3] - __bfloat162float(h3)));
    lo.x = *(uint32_t*)&c;  lo.y = *(uint32_t*)&d;
}

__inline__ __device__ float warpMax(float v) {
#pragma unroll
    for (int o = 16; o; o >>= 1) v = fmaxf(v, __shfl_xor_sync(0xffffffffu, v, o));
    return v;
}
__inline__ __device__ float warpSum(float v) {
#pragma unroll
    for (int o = 16; o; o >>= 1) v += __shfl_xor_sync(0xffffffffu, v, o);
    return v;
}

// ---------------------------------------------------------------------------
// bf16x3 GEMM. Inner loop reordered: per mi, each of the 3 split-terms is
// issued across all 4 ni before the next term touches the same accumulator,
// so same-acc MMAs are 4 independent MMAs apart (was: 3 back-to-back RAW).
// Per-accumulator accumulation order unchanged (hh, hl, lh) -> bitwise
// identical results to R12.
// ---------------------------------------------------------------------------
#define STAGE_BYTES 32768
#define NSTAGE 3
#define GEMM_SMEM (NSTAGE * STAGE_BYTES)   // 96 KB -> 2 CTAs/SM

template <int OUT>
__global__ __launch_bounds__(256, 2)
void gemm_bf16x3(const __nv_bfloat16* __restrict__ Ah, const __nv_bfloat16* __restrict__ Al,
                 const __nv_bfloat16* __restrict__ Bh, const __nv_bfloat16* __restrict__ Bl,
                 float* __restrict__ C,
                 __nv_bfloat16* __restrict__ Oh, __nv_bfloat16* __restrict__ Ol,
                 int K, int ldc, long sA, long sB, long sC)
{
    extern __shared__ __align__(1024) char smem[];
    const uint32_t sb = s2u(smem);
    const int tid  = threadIdx.x;
    const int lane = tid & 31;
    const int wid  = tid >> 5;
    const int wm   = wid & 1;
    const int wn   = wid >> 1;
    const long bm  = (long)blockIdx.y * 128;
    const long bn  = (long)blockIdx.x * 128;

    Ah += blockIdx.z * sA + bm * K;  Al += blockIdx.z * sA + bm * K;
    Bh += blockIdx.z * sB + bn * K;  Bl += blockIdx.z * sB + bn * K;

    const int NS = K >> 5;

    float acc[4][4][4];
#pragma unroll
    for (int mi = 0; mi < 4; mi++)
#pragma unroll
        for (int ni = 0; ni < 4; ni++)
#pragma unroll
            for (int r = 0; r < 4; r++) acc[mi][ni][r] = 0.f;

    auto load_stage = [&](int kb, int slot) {
        const uint32_t st = sb + slot * STAGE_BYTES;
        const long gk = (long)kb * 32;
#pragma unroll
        for (int j = 0; j < 2; j++) {
            const int c   = tid + j * 256;
            const int row = c >> 2;
            const int kc  = c & 3;
            const uint32_t so =
                swz((uint32_t)((row & 63) * 128 + (row >> 6) * 64 + kc * 16));
            const long go = (long)row * K + gk + kc * 8;
            cp16(st +          so, Ah + go);
            cp16(st +  8192 +  so, Al + go);
            cp16(st + 16384 +  so, Bh + go);
            cp16(st + 24576 +  so, Bl + go);
        }
    };

    auto b_addr = [&](uint32_t st, int ks, int nipair) -> uint32_t {
        const int g = lane >> 3, l = lane & 7;
        const int n = wn * 32 + nipair * 16 + (g >> 1) * 8 + l;
        const uint32_t kbyte = (uint32_t)(ks * 32 + (g & 1) * 16);
        return st + swz((uint32_t)((n & 63) * 128 + (n >> 6) * 64) + kbyte);
    };

    auto compute_stage = [&](int slot) {
        const uint32_t st = sb + slot * STAGE_BYTES;
#pragma unroll
        for (int ks = 0; ks < 2; ks++) {
            uint32_t bhf[2][4], blf[2][4];
#pragma unroll
            for (int np = 0; np < 2; np++) {
                const uint32_t ba = b_addr(st, ks, np);
                ldsm4(bhf[np], 16384 + ba);
                ldsm4(blf[np],  24576 + ba);
            }
#pragma unroll
            for (int mi = 0; mi < 4; mi++) {
                uint32_t ahf[4], alf[4];
                const uint32_t off = swz((uint32_t)(
                    (mi * 16 + (lane & 15)) * 128 + wm * 64 + ks * 32 + ((lane >> 4) << 4)));
                ldsm4(ahf, st + off);
                ldsm4(alf, st + 8192 + off);
                // term hh across all ni (independent accumulators)
#pragma unroll
                for (int ni = 0; ni < 4; ni++)
                    mma16816(acc[mi][ni], ahf, &bhf[ni >> 1][(ni & 1) * 2]);
                // term hl
#pragma unroll
                for (int ni = 0; ni < 4; ni++)
                    mma16816(acc[mi][ni], ahf, &blf[ni >> 1][(ni & 1) * 2]);
                // term lh
#pragma unroll
                for (int ni = 0; ni < 4; ni++)
                    mma16816(acc[mi][ni], alf, &bhf[ni >> 1][(ni & 1) * 2]);
            }
        }
    };

    load_stage(0, 0); CP_COMMIT();
    load_stage(1, 1); CP_COMMIT();

    for (int kb = 0; kb < NS; kb++) {
        CP_WAIT(1);
        __syncthreads();
        if (kb + 2 < NS) load_stage(kb + 2, (kb + 2) % 3);
        CP_COMMIT();
        compute_stage(kb % 3);
    }

    if (OUT == 0) {
        C += blockIdx.z * sC;
#pragma unroll
        for (int mi = 0; mi < 4; mi++) {
            const long r0 = bm + wm * 64 + mi * 16 + (lane >> 2);
#pragma unroll
            for (int ni = 0; ni < 4; ni++) {
                const long c = bn + wn * 32 + ni * 8 + (lane & 3) * 2;
                *(float2*)(C + r0 * ldc + c) =
                    make_float2(acc[mi][ni][0], acc[mi][ni][1]);
                *(float2*)(C + (r0 + 8) * ldc + c) =
                    make_float2(acc[mi][ni][2], acc[mi][ni][3]);
            }
        }
    } else {
        Oh += blockIdx.z * sC;  Ol += blockIdx.z * sC;
#pragma unroll
        for (int mi = 0; mi < 4; mi++) {
            const long r0 = bm + wm * 64 + mi * 16 + (lane >> 2);
#pragma unroll
            for (int ni = 0; ni < 4; ni++) {
                const long c = bn + wn * 32 + ni * 8 + (lane & 3) * 2;
#pragma unroll
                for (int p = 0; p < 2; p++) {
                    const long r = r0 + p * 8;
                    float vx = acc[mi][ni][2 * p], vy = acc[mi][ni][2 * p + 1];
                    __nv_bfloat16 hx = __float2bfloat16(vx);
                    __nv_bfloat16 hy = __float2bfloat16(vy);
                    __nv_bfloat16 lx = __float2bfloat16(vx - __bfloat162float(hx));
                    __nv_bfloat16 ly = __float2bfloat16(vy - __bfloat162float(hy));
                    *(__nv_bfloat162*)(Oh + r * ldc + c) = __nv_bfloat162(hx, hy);
                    *(__nv_bfloat162*)(Ol + r * ldc + c) = __nv_bfloat162(lx, ly);
                }
            }
        }
    }
}

// ---------------------------------------------------------------------------
// Elementwise fp32 -> bf16 hi/lo split (weights only)
// ---------------------------------------------------------------------------
__global__ void split_elem(const float* __restrict__ s,
                           __nv_bfloat16* __restrict__ h,
                           __nv_bfloat16* __restrict__ l, long n)
{
    long i = (long)blockIdx.x * blockDim.x + threadIdx.x;
    if (i >= n) return;
    float v = s[i];
    __nv_bfloat16 hi = __float2bfloat16(v);
    h[i] = hi;
    l[i] = __float2bfloat16(v - __bfloat162float(hi));
}

// ---------------------------------------------------------------------------
// Transpose + bf16 split for input x: src[C,T] -> dst[T,C]
// ---------------------------------------------------------------------------
__global__ void tsplit_kernel(const float* __restrict__ src,
                              __nv_bfloat16* __restrict__ dh,
                              __nv_bfloat16* __restrict__ dl)
{
    __shared__ float tile[32][33];
    const int b   = blockIdx.z;
    const int t0  = blockIdx.x * 32;
    const int c0  = blockIdx.y * 32;
    const int tid = threadIdx.x;
    const float* s = src + (long)b * NC * NT;

    {
        const int c  = tid >> 3;
        const int tc = tid & 7;
        float4 v = *(const float4*)(s + (long)(c0 + c) * NT + t0 + tc * 4);
        tile[c][tc * 4 + 0] = v.x;
        tile[c][tc * 4 + 1] = v.y;
        tile[c][tc * 4 + 2] = v.z;
        tile[c][tc * 4 + 3] = v.w;
    }
    __syncthreads();

    {
        const int tq  = tid >> 3;
        const int cch = tid & 7;
        const int tt  = t0 + tq;
        float v[4];
#pragma unroll
        for (int i = 0; i < 4; i++) v[i] = tile[cch * 4 + i][tq];
        uint2 hi, lo;
        split4(v, hi, lo);
        const long o = (long)b * NT * NC + (long)tt * NC + c0 + cch * 4;
        *(uint2*)(dh + o) = hi;
        *(uint2*)(dl + o) = lo;
    }
}

// ---------------------------------------------------------------------------
// FUSED q/k path: dwconv + per-token L2 norm + scaled transpose + bf16 split.
// ---------------------------------------------------------------------------
#define QK_SMEM (32 * 513 * 4 + 128)

__global__ __launch_bounds__(256)
void qk_fuse_kernel(const float* __restrict__ qkv,
                    const float* __restrict__ w,
                    __nv_bfloat16* __restrict__ qh, __nv_bfloat16* __restrict__ ql,
                    __nv_bfloat16* __restrict__ kh, __nv_bfloat16* __restrict__ kl)
{
    extern __shared__ float smf[];
    float (*tile)[513] = (float (*)[513])smf;
    float* sinv = smf + 32 * 513;

    const int sel = blockIdx.z;        // 0=q, 1=k
    const int b   = blockIdx.y;
    const int t0  = blockIdx.x * 32;
    const int tid = threadIdx.x;
    const int lane = tid & 31;
    const int wid  = tid >> 5;

    const float* src = qkv + (long)b * N3C * NT + (long)sel * NC * NT;
    const float* wch = w + (long)sel * NC * 3;

#pragma unroll
    for (int it = 0; it < 16; it++) {
        const int idx = tid + it * 256;
        const int c   = idx >> 3;
        const int t4  = idx & 7;
        const long base = (long)c * NT + t0 + t4 * 4;
        const int tg = t0 + t4 * 4;
        const float4 cur = *(const float4*)(src + base);
        const float prev = (tg > 0)       ? src[base - 1] : 0.f;
        const float nxt  = (tg + 4 < NT)  ? src[base + 4] : 0.f;
        const float w0 = wch[c * 3 + 0], w1 = wch[c * 3 + 1], w2 = wch[c * 3 + 2];
        tile[t4 * 4 + 0][c] = w0 * prev  + w1 * cur.x + w2 * cur.y;
        tile[t4 * 4 + 1][c] = w0 * cur.x + w1 * cur.y + w2 * cur.z;
        tile[t4 * 4 + 2][c] = w0 * cur.y + w1 * cur.z + w2 * cur.w;
        tile[t4 * 4 + 3][c] = w0 * cur.z + w1 * cur.w + w2 * nxt;
    }
    __syncthreads();

    const float scale0 = (sel == 0) ? TEMP_INV : 1.f;
#pragma unroll
    for (int j = 0; j < 4; j++) {
        const int t = wid * 4 + j;
        float s = 0.f;
#pragma unroll
        for (int u = 0; u < 16; u++) {
            const float v = tile[t][lane + u * 32];
            s += v * v;
        }
        s = warpSum(s);
        if (lane == 0) sinv[t] = scale0 / fmaxf(sqrtf(s), L2EPS);
    }
    __syncthreads();

    __nv_bfloat16* dh = (sel == 0) ? qh : kh;
    __nv_bfloat16* dl = (sel == 0) ? ql : kl;
    const int t  = tid >> 3;
    const int c8 = tid & 7;
    const float sc = sinv[t];
    const long orow = (long)b * NT * NC + (long)(t0 + t) * NC;
#pragma unroll
    for (int it = 0; it < 16; it++) {
        const int c = (c8 + it * 8) * 4;
        float v[4];
#pragma unroll
        for (int i = 0; i < 4; i++) v[i] = tile[t][c + i] * sc;
        uint2 hi, lo;
        split4(v, hi, lo);
        *(uint2*)(dh + orow + c) = hi;
        *(uint2*)(dl + orow + c) = lo;
    }
}

// ---------------------------------------------------------------------------
// Depthwise conv for V channels only -> bf16 hi/lo packed
// ---------------------------------------------------------------------------
__global__ void vdw_kernel(const float* __restrict__ qkv,
                           const float* __restrict__ w,
                           __nv_bfloat16* __restrict__ vh,
                           __nv_bfloat16* __restrict__ vl)
{
    const long total4 = (long)NB * NC * (NT / 4);
    long i4 = (long)blockIdx.x * blockDim.x + threadIdx.x;
    if (i4 >= total4) return;
    const int t4 = (int)(i4 % (NT / 4));
    const int ch = (int)((i4 / (NT / 4)) % NC);
    const int b  = (int)(i4 / ((long)NC * (NT / 4)));
    const long base = (long)b * N3C * NT + (long)(2 * NC + ch) * NT;
    const int t0 = t4 * 4;

    const float4 cur = *(const float4*)(qkv + base + t0);
    const float prev = (t0 > 0)       ? qkv[base + t0 - 1] : 0.f;
    const float nxt  = (t0 + 4 < NT)  ? qkv[base + t0 + 4] : 0.f;
    const int wc = (2 * NC + ch) * 3;
    const float w0 = w[wc + 0], w1 = w[wc + 1], w2 = w[wc + 2];

    float o[4];
    o[0] = w0 * prev  + w1 * cur.x + w2 * cur.y;
    o[1] = w0 * cur.x + w1 * cur.y + w2 * cur.z;
    o[2] = w0 * cur.y + w1 * cur.z + w2 * cur.w;
    o[3] = w0 * cur.z + w1 * cur.w + w2 * nxt;

    const long oo = (long)b * NC * NT + (long)ch * NT + t0;
    uint2 hi, lo;
    split4(o, hi, lo);
    *(uint2*)(vh + oo) = hi;
    *(uint2*)(vl + oo) = lo;
}

// ---------------------------------------------------------------------------
// Row softmax over T, float4 loads, packed bf16 hi/lo stores
// ---------------------------------------------------------------------------
__global__ void softmax_split_kernel(const float* __restrict__ scores,
                                     __nv_bfloat16* __restrict__ ah,
                                     __nv_bfloat16* __restrict__ al)
{
    const long row = blockIdx.x;
    const float4* p4 = (const float4*)(scores + row * NT);
    const int tid  = threadIdx.x;
    const int lane = tid & 31;
    const int wid  = tid >> 5;
    __shared__ float red[8];

    float4 va = p4[tid], vb = p4[tid + 256];
    float vals[8] = {va.x, va.y, va.z, va.w, vb.x, vb.y, vb.z, vb.w};

    float m = -1e30f;
#pragma unroll
    for (int i = 0; i < 8; i++) m = fmaxf(m, vals[i]);
    m = warpMax(m);
    if (lane == 0) red[wid] = m;
    __syncthreads();
    if (wid == 0) {
        float v = (lane < 8) ? red[lane] : -1e30f;
        v = warpMax(v);
        if (lane == 0) red[0] = v;
    }
    __syncthreads();
    m = red[0];
    __syncthreads();

    float s = 0.f;
#pragma unroll
    for (int i = 0; i < 8; i++) { vals[i] = __expf(vals[i] - m); s += vals[i]; }
    s = warpSum(s);
    if (lane == 0) red[wid] = s;
    __syncthreads();
    if (wid == 0) {
        float v = (lane < 8) ? red[lane] : 0.f;
        v = warpSum(v);
        if (lane == 0) red[0] = v;
    }
    __syncthreads();
    const float inv = 1.f / red[0];

#pragma unroll
    for (int g = 0; g < 2; g++) {
        float v[4];
#pragma unroll
        for (int i = 0; i < 4; i++) v[i] = vals[g * 4 + i] * inv;
        uint2 hi, lo;
        split4(v, hi, lo);
        const long o = row * NT + (long)(tid + g * 256) * 4;
        *(uint2*)(ah + o) = hi;
        *(uint2*)(al + o) = lo;
    }
}

// ---------------------------------------------------------------------------
// Launch
// ---------------------------------------------------------------------------
extern "C" void kernel_launch(void* const* d_in, const int* in_sizes, int n_in,
                              void* d_out, int out_size)
{
    const float* x      = (const float*)d_in[0];
    const float* w_qkv  = (const float*)d_in[1];
    const float* w_dw   = (const float*)d_in[2];
    const float* w_proj = (const float*)d_in[3];
    float* out = (float*)d_out;

    cudaFuncSetAttribute(gemm_bf16x3<0>, cudaFuncAttributeMaxDynamicSharedMemorySize, GEMM_SMEM);
    cudaFuncSetAttribute(gemm_bf16x3<1>, cudaFuncAttributeMaxDynamicSharedMemorySize, GEMM_SMEM);
    cudaFuncSetAttribute(qk_fuse_kernel, cudaFuncAttributeMaxDynamicSharedMemorySize, QK_SMEM);

    float *qkv, *scores;
    cudaGetSymbolAddress((void**)&qkv,    g_qkv);
    cudaGetSymbolAddress((void**)&scores, g_scores);

    __nv_bfloat16 *wqh, *wql, *wph, *wpl, *xth, *xtl, *qth, *qtl, *kth, *ktl,
                  *vh, *vl, *ath, *atl, *oth, *otl;
    cudaGetSymbolAddress((void**)&wqh, g_wq_h);  cudaGetSymbolAddress((void**)&wql, g_wq_l);
    cudaGetSymbolAddress((void**)&wph, g_wp_h);  cudaGetSymbolAddress((void**)&wpl, g_wp_l);
    cudaGetSymbolAddress((void**)&xth, g_xT_h);  cudaGetSymbolAddress((void**)&xtl, g_xT_l);
    cudaGetSymbolAddress((void**)&qth, g_qT_h);  cudaGetSymbolAddress((void**)&qtl, g_qT_l);
    cudaGetSymbolAddress((void**)&kth, g_kT_h);  cudaGetSymbolAddress((void**)&ktl, g_kT_l);
    cudaGetSymbolAddress((void**)&vh,  g_v_h);   cudaGetSymbolAddress((void**)&vl,  g_v_l);
    cudaGetSymbolAddress((void**)&ath, g_at_h);  cudaGetSymbolAddress((void**)&atl, g_at_l);
    cudaGetSymbolAddress((void**)&oth, g_oT_h);  cudaGetSymbolAddress((void**)&otl, g_oT_l);

    // weight splits
    split_elem<<<(unsigned)(((long)N3C * NC + 255) / 256), 256>>>(w_qkv, wqh, wql, (long)N3C * NC);
    split_elem<<<(unsigned)(((long)NC * NC + 255) / 256), 256>>>(w_proj, wph, wpl, (long)NC * NC);

    // xT split (transpose [C,T] -> [T,C])
    {
        dim3 grid(NT / 32, NC / 32, NB);
        tsplit_kernel<<<grid, 256>>>(x, xth, xtl);
    }

    // 1) qkv = W_qkv @ x : M=1536, N=2048, K=512 -> fp32
    {
        dim3 grid(NT / 128, N3C / 128, NB);
        gemm_bf16x3<0><<<grid, 256, GEMM_SMEM>>>(wqh, wql, xth, xtl, qkv, nullptr, nullptr,
            512, NT, 0L, (long)NT * NC, (long)N3C * NT);
    }

    // 2) fused dwconv + L2norm + transpose-split for q,k
    {
        dim3 grid(NT / 32, NB, 2);
        qk_fuse_kernel<<<grid, 256, QK_SMEM>>>(qkv, w_dw, qth, qtl, kth, ktl);
    }

    // 3) dwconv for v -> bf16 hi/lo
    {
        const long total4 = (long)NB * NC * (NT / 4);
        vdw_kernel<<<(unsigned)((total4 + 255) / 256), 256>>>(qkv, w_dw, vh, vl);
    }

    // 4) scores = qT @ kT^T : M=N=2048, K=512 -> fp32
    {
        dim3 grid(NT / 128, NT / 128, NB);
        gemm_bf16x3<0><<<grid, 256, GEMM_SMEM>>>(qth, qtl, kth, ktl, scores, nullptr, nullptr,
            512, NT, (long)NT * NC, (long)NT * NC, (long)NT * NT);
    }

    // 5) softmax + bf16 split
    softmax_split_kernel<<<NB * NT, 256>>>(scores, ath, atl);

    // 6) outT = attn @ v^T : M=2048, N=512, K=2048 -> bf16 hi/lo direct
    {
        dim3 grid(NC / 128, NT / 128, NB);
        gemm_bf16x3<1><<<grid, 256, GEMM_SMEM>>>(ath, atl, vh, vl, nullptr, oth, otl,
            2048, NC, (long)NT * NT, (long)NC * NT, (long)NT * NC);
    }

    // 7) final = W_proj @ outT^T : M=512, N=2048, K=512 -> fp32 d_out
    {
        dim3 grid(NT / 128, NC / 128, NB);
        gemm_bf16x3<0><<<grid, 256, GEMM_SMEM>>>(wph, wpl, oth, otl, out, nullptr, nullptr,
            512, NT, 0L, (long)NT * NC, (long)NC * NT);
    }
}

// round 14
// speedup vs baseline: 1.0400x; 1.0400x over previous
#include <cuda_runtime.h>
#include <cuda_bf16.h>
#include <math.h>
#include <stdint.h>

// Problem constants
#define NB 8
#define NC 512
#define NT 2048
#define N3C 1536
#define TEMP_INV (1.0f / 0.07f)
#define L2EPS 1e-12f

// ---------------------------------------------------------------------------
// Static scratch (no allocation allowed anywhere)
// ---------------------------------------------------------------------------
__device__ float g_qkv   [(size_t)NB * N3C * NT];
__device__ float g_scores[(size_t)NB * NT  * NT];

__device__ __nv_bfloat16 g_wq_h[(size_t)N3C * NC], g_wq_l[(size_t)N3C * NC];
__device__ __nv_bfloat16 g_wp_h[(size_t)NC  * NC], g_wp_l[(size_t)NC  * NC];
__device__ __nv_bfloat16 g_xT_h[(size_t)NB * NT * NC], g_xT_l[(size_t)NB * NT * NC];
__device__ __nv_bfloat16 g_qT_h[(size_t)NB * NT * NC], g_qT_l[(size_t)NB * NT * NC];
__device__ __nv_bfloat16 g_kT_h[(size_t)NB * NT * NC], g_kT_l[(size_t)NB * NT * NC];
__device__ __nv_bfloat16 g_v_h [(size_t)NB * NC * NT], g_v_l [(size_t)NB * NC * NT];
__device__ __nv_bfloat16 g_at_h[(size_t)NB * NT * NT], g_at_l[(size_t)NB * NT * NT];
__device__ __nv_bfloat16 g_oT_h[(size_t)NB * NT * NC], g_oT_l[(size_t)NB * NT * NC];

// ---------------------------------------------------------------------------
// PTX helpers (baseline sm_80+ only)
// ---------------------------------------------------------------------------
__device__ __forceinline__ uint32_t s2u(const void* p) {
    uint32_t a;
    asm("{ .reg .u64 t; cvta.to.shared.u64 t, %1; cvt.u32.u64 %0, t; }"
        : "=r"(a) : "l"(p));
    return a;
}

__device__ __forceinline__ void cp16(uint32_t s, const void* g) {
    asm volatile("cp.async.cg.shared.global [%0], [%1], 16;" :: "r"(s), "l"(g));
}
#define CP_COMMIT() asm volatile("cp.async.commit_group;" ::: "memory")
#define CP_WAIT(n)  asm volatile("cp.async.wait_group %0;" :: "n"(n) : "memory")

__device__ __forceinline__ void ldsm4(uint32_t* r, uint32_t a) {
    asm volatile("ldmatrix.sync.aligned.m8n8.x4.shared.b16 {%0,%1,%2,%3}, [%4];"
                 : "=r"(r[0]), "=r"(r[1]), "=r"(r[2]), "=r"(r[3]) : "r"(a));
}

// R12 exact: volatile — known-good schedule at tensor=66%.
__device__ __forceinline__ void mma16816(float* c, const uint32_t* a, const uint32_t* b) {
    asm volatile(
        "mma.sync.aligned.m16n8k16.row.col.f32.bf16.bf16.f32 "
        "{%0,%1,%2,%3}, {%4,%5,%6,%7}, {%8,%9}, {%0,%1,%2,%3};"
        : "+f"(c[0]), "+f"(c[1]), "+f"(c[2]), "+f"(c[3])
        : "r"(a[0]), "r"(a[1]), "r"(a[2]), "r"(a[3]), "r"(b[0]), "r"(b[1]));
}

// 128-byte-row XOR swizzle
__device__ __forceinline__ uint32_t swz(uint32_t b) {
    return b ^ (((b >> 7) & 7) << 4);
}

__device__ __forceinline__ void split4(const float* v, uint2& hi, uint2& lo) {
    __nv_bfloat16 h0 = __float2bfloat16(v[0]);
    __nv_bfloat16 h1 = __float2bfloat16(v[1]);
    __nv_bfloat16 h2 = __float2bfloat16(v[2]);
    __nv_bfloat16 h3 = __float2bfloat16(v[3]);
    __nv_bfloat162 a = __nv_bfloat162(h0, h1), b = __nv_bfloat162(h2, h3);
    hi.x = *(uint32_t*)&a;  hi.y = *(uint32_t*)&b;
    __nv_bfloat162 c = __nv_bfloat162(__float2bfloat16(v[0] - __bfloat162float(h0)),
                                      __float2bfloat16(v[1] - __bfloat162float(h1)));
    __nv_bfloat162 d = __nv_bfloat162(__float2bfloat16(v[2] - __bfloat162float(h2)),
                                      __float2bfloat16(v[3] - __bfloat162float(h3)));
    lo.x = *(uint32_t*)&c;  lo.y = *(uint32_t*)&d;
}

__inline__ __device__ float warpMax(float v) {
#pragma unroll
    for (int o = 16; o; o >>= 1) v = fmaxf(v, __shfl_xor_sync(0xffffffffu, v, o));
    return v;
}
__inline__ __device__ float warpSum(float v) {
#pragma unroll
    for (int o = 16; o; o >>= 1) v += __shfl_xor_sync(0xffffffffu, v, o);
    return v;
}

// ---------------------------------------------------------------------------
// bf16x3 GEMM — R12 exact (known-good 895us config, tensor=66%)
// ---------------------------------------------------------------------------
#define STAGE_BYTES 32768
#define NSTAGE 3
#define GEMM_SMEM (NSTAGE * STAGE_BYTES)   // 96 KB -> 2 CTAs/SM

template <int OUT>
__global__ __launch_bounds__(256, 2)
void gemm_bf16x3(const __nv_bfloat16* __restrict__ Ah, const __nv_bfloat16* __restrict__ Al,
                 const __nv_bfloat16* __restrict__ Bh, const __nv_bfloat16* __restrict__ Bl,
                 float* __restrict__ C,
                 __nv_bfloat16* __restrict__ Oh, __nv_bfloat16* __restrict__ Ol,
                 int K, int ldc, long sA, long sB, long sC)
{
    extern __shared__ __align__(1024) char smem[];
    const uint32_t sb = s2u(smem);
    const int tid  = threadIdx.x;
    const int lane = tid & 31;
    const int wid  = tid >> 5;
    const int wm   = wid & 1;
    const int wn   = wid >> 1;
    const long bm  = (long)blockIdx.y * 128;
    const long bn  = (long)blockIdx.x * 128;

    Ah += blockIdx.z * sA + bm * K;  Al += blockIdx.z * sA + bm * K;
    Bh += blockIdx.z * sB + bn * K;  Bl += blockIdx.z * sB + bn * K;

    const int NS = K >> 5;

    float acc[4][4][4];
#pragma unroll
    for (int mi = 0; mi < 4; mi++)
#pragma unroll
        for (int ni = 0; ni < 4; ni++)
#pragma unroll
            for (int r = 0; r < 4; r++) acc[mi][ni][r] = 0.f;

    auto load_stage = [&](int kb, int slot) {
        const uint32_t st = sb + slot * STAGE_BYTES;
        const long gk = (long)kb * 32;
#pragma unroll
        for (int j = 0; j < 2; j++) {
            const int c   = tid + j * 256;
            const int row = c >> 2;
            const int kc  = c & 3;
            const uint32_t so =
                swz((uint32_t)((row & 63) * 128 + (row >> 6) * 64 + kc * 16));
            const long go = (long)row * K + gk + kc * 8;
            cp16(st +          so, Ah + go);
            cp16(st +  8192 +  so, Al + go);
            cp16(st + 16384 +  so, Bh + go);
            cp16(st + 24576 +  so, Bl + go);
        }
    };

    auto b_addr = [&](uint32_t st, int ks, int nipair) -> uint32_t {
        const int g = lane >> 3, l = lane & 7;
        const int n = wn * 32 + nipair * 16 + (g >> 1) * 8 + l;
        const uint32_t kbyte = (uint32_t)(ks * 32 + (g & 1) * 16);
        return st + swz((uint32_t)((n & 63) * 128 + (n >> 6) * 64) + kbyte);
    };

    auto compute_stage = [&](int slot) {
        const uint32_t st = sb + slot * STAGE_BYTES;
#pragma unroll
        for (int ks = 0; ks < 2; ks++) {
            uint32_t bhf[2][4], blf[2][4];
#pragma unroll
            for (int np = 0; np < 2; np++) {
                const uint32_t ba = b_addr(st, ks, np);
                ldsm4(bhf[np], 16384 + ba);
                ldsm4(blf[np],  24576 + ba);
            }
#pragma unroll
            for (int mi = 0; mi < 4; mi++) {
                uint32_t ahf[4], alf[4];
                const uint32_t off = swz((uint32_t)(
                    (mi * 16 + (lane & 15)) * 128 + wm * 64 + ks * 32 + ((lane >> 4) << 4)));
                ldsm4(ahf, st + off);
                ldsm4(alf, st + 8192 + off);
#pragma unroll
                for (int ni = 0; ni < 4; ni++) {
                    const uint32_t* bh = &bhf[ni >> 1][(ni & 1) * 2];
                    const uint32_t* bl = &blf[ni >> 1][(ni & 1) * 2];
                    mma16816(acc[mi][ni], ahf, bh);
                    mma16816(acc[mi][ni], ahf, bl);
                    mma16816(acc[mi][ni], alf, bh);
                }
            }
        }
    };

    load_stage(0, 0); CP_COMMIT();
    load_stage(1, 1); CP_COMMIT();

    for (int kb = 0; kb < NS; kb++) {
        CP_WAIT(1);
        __syncthreads();
        if (kb + 2 < NS) load_stage(kb + 2, (kb + 2) % 3);
        CP_COMMIT();
        compute_stage(kb % 3);
    }

    if (OUT == 0) {
        C += blockIdx.z * sC;
#pragma unroll
        for (int mi = 0; mi < 4; mi++) {
            const long r0 = bm + wm * 64 + mi * 16 + (lane >> 2);
#pragma unroll
            for (int ni = 0; ni < 4; ni++) {
                const long c = bn + wn * 32 + ni * 8 + (lane & 3) * 2;
                *(float2*)(C + r0 * ldc + c) =
                    make_float2(acc[mi][ni][0], acc[mi][ni][1]);
                *(float2*)(C + (r0 + 8) * ldc + c) =
                    make_float2(acc[mi][ni][2], acc[mi][ni][3]);
            }
        }
    } else {
        Oh += blockIdx.z * sC;  Ol += blockIdx.z * sC;
#pragma unroll
        for (int mi = 0; mi < 4; mi++) {
            const long r0 = bm + wm * 64 + mi * 16 + (lane >> 2);
#pragma unroll
            for (int ni = 0; ni < 4; ni++) {
                const long c = bn + wn * 32 + ni * 8 + (lane & 3) * 2;
#pragma unroll
                for (int p = 0; p < 2; p++) {
                    const long r = r0 + p * 8;
                    float vx = acc[mi][ni][2 * p], vy = acc[mi][ni][2 * p + 1];
                    __nv_bfloat16 hx = __float2bfloat16(vx);
                    __nv_bfloat16 hy = __float2bfloat16(vy);
                    __nv_bfloat16 lx = __float2bfloat16(vx - __bfloat162float(hx));
                    __nv_bfloat16 ly = __float2bfloat16(vy - __bfloat162float(hy));
                    *(__nv_bfloat162*)(Oh + r * ldc + c) = __nv_bfloat162(hx, hy);
                    *(__nv_bfloat162*)(Ol + r * ldc + c) = __nv_bfloat162(lx, ly);
                }
            }
        }
    }
}

// ---------------------------------------------------------------------------
// Both weight splits in ONE launch (w_qkv: n1 elems, then w_proj: n2 elems)
// ---------------------------------------------------------------------------
__global__ void split_weights(const float* __restrict__ s1, __nv_bfloat16* __restrict__ h1,
                              __nv_bfloat16* __restrict__ l1, long n1,
                              const float* __restrict__ s2, __nv_bfloat16* __restrict__ h2,
                              __nv_bfloat16* __restrict__ l2, long n2)
{
    long i = (long)blockIdx.x * blockDim.x + threadIdx.x;
    const float* s; __nv_bfloat16 *h, *l;
    if (i < n1) { s = s1; h = h1; l = l1; }
    else if (i < n1 + n2) { i -= n1; s = s2; h = h2; l = l2; }
    else return;
    float v = s[i];
    __nv_bfloat16 hi = __float2bfloat16(v);
    h[i] = hi;
    l[i] = __float2bfloat16(v - __bfloat162float(hi));
}

// ---------------------------------------------------------------------------
// Transpose + bf16 split for input x: src[C,T] -> dst[T,C]
// ---------------------------------------------------------------------------
__global__ void tsplit_kernel(const float* __restrict__ src,
                              __nv_bfloat16* __restrict__ dh,
                              __nv_bfloat16* __restrict__ dl)
{
    __shared__ float tile[32][33];
    const int b   = blockIdx.z;
    const int t0  = blockIdx.x * 32;
    const int c0  = blockIdx.y * 32;
    const int tid = threadIdx.x;
    const float* s = src + (long)b * NC * NT;

    {
        const int c  = tid >> 3;
        const int tc = tid & 7;
        float4 v = *(const float4*)(s + (long)(c0 + c) * NT + t0 + tc * 4);
        tile[c][tc * 4 + 0] = v.x;
        tile[c][tc * 4 + 1] = v.y;
        tile[c][tc * 4 + 2] = v.z;
        tile[c][tc * 4 + 3] = v.w;
    }
    __syncthreads();

    {
        const int tq  = tid >> 3;
        const int cch = tid & 7;
        const int tt  = t0 + tq;
        float v[4];
#pragma unroll
        for (int i = 0; i < 4; i++) v[i] = tile[cch * 4 + i][tq];
        uint2 hi, lo;
        split4(v, hi, lo);
        const long o = (long)b * NT * NC + (long)tt * NC + c0 + cch * 4;
        *(uint2*)(dh + o) = hi;
        *(uint2*)(dl + o) = lo;
    }
}

// ---------------------------------------------------------------------------
// FUSED q/k path: dwconv + per-token L2 norm + scaled transpose + bf16 split.
// ---------------------------------------------------------------------------
#define QK_SMEM (32 * 513 * 4 + 128)

__global__ __launch_bounds__(256)
void qk_fuse_kernel(const float* __restrict__ qkv,
                    const float* __restrict__ w,
                    __nv_bfloat16* __restrict__ qh, __nv_bfloat16* __restrict__ ql,
                    __nv_bfloat16* __restrict__ kh, __nv_bfloat16* __restrict__ kl)
{
    extern __shared__ float smf[];
    float (*tile)[513] = (float (*)[513])smf;
    float* sinv = smf + 32 * 513;

    const int sel = blockIdx.z;        // 0=q, 1=k
    const int b   = blockIdx.y;
    const int t0  = blockIdx.x * 32;
    const int tid = threadIdx.x;
    const int lane = tid & 31;
    const int wid  = tid >> 5;

    const float* src = qkv + (long)b * N3C * NT + (long)sel * NC * NT;
    const float* wch = w + (long)sel * NC * 3;

#pragma unroll
    for (int it = 0; it < 16; it++) {
        const int idx = tid + it * 256;
        const int c   = idx >> 3;
        const int t4  = idx & 7;
        const long base = (long)c * NT + t0 + t4 * 4;
        const int tg = t0 + t4 * 4;
        const float4 cur = *(const float4*)(src + base);
        const float prev = (tg > 0)       ? src[base - 1] : 0.f;
        const float nxt  = (tg + 4 < NT)  ? src[base + 4] : 0.f;
        const float w0 = wch[c * 3 + 0], w1 = wch[c * 3 + 1], w2 = wch[c * 3 + 2];
        tile[t4 * 4 + 0][c] = w0 * prev  + w1 * cur.x + w2 * cur.y;
        tile[t4 * 4 + 1][c] = w0 * cur.x + w1 * cur.y + w2 * cur.z;
        tile[t4 * 4 + 2][c] = w0 * cur.y + w1 * cur.z + w2 * cur.w;
        tile[t4 * 4 + 3][c] = w0 * cur.z + w1 * cur.w + w2 * nxt;
    }
    __syncthreads();

    const float scale0 = (sel == 0) ? TEMP_INV : 1.f;
#pragma unroll
    for (int j = 0; j < 4; j++) {
        const int t = wid * 4 + j;
        float s = 0.f;
#pragma unroll
        for (int u = 0; u < 16; u++) {
            const float v = tile[t][lane + u * 32];
            s += v * v;
        }
        s = warpSum(s);
        if (lane == 0) sinv[t] = scale0 / fmaxf(sqrtf(s), L2EPS);
    }
    __syncthreads();

    __nv_bfloat16* dh = (sel == 0) ? qh : kh;
    __nv_bfloat16* dl = (sel == 0) ? ql : kl;
    const int t  = tid >> 3;
    const int c8 = tid & 7;
    const float sc = sinv[t];
    const long orow = (long)b * NT * NC + (long)(t0 + t) * NC;
#pragma unroll
    for (int it = 0; it < 16; it++) {
        const int c = (c8 + it * 8) * 4;
        float v[4];
#pragma unroll
        for (int i = 0; i < 4; i++) v[i] = tile[t][c + i] * sc;
        uint2 hi, lo;
        split4(v, hi, lo);
        *(uint2*)(dh + orow + c) = hi;
        *(uint2*)(dl + orow + c) = lo;
    }
}

// ---------------------------------------------------------------------------
// Depthwise conv for V channels only -> bf16 hi/lo packed
// ---------------------------------------------------------------------------
__global__ void vdw_kernel(const float* __restrict__ qkv,
                           const float* __restrict__ w,
                           __nv_bfloat16* __restrict__ vh,
                           __nv_bfloat16* __restrict__ vl)
{
    const long total4 = (long)NB * NC * (NT / 4);
    long i4 = (long)blockIdx.x * blockDim.x + threadIdx.x;
    if (i4 >= total4) return;
    const int t4 = (int)(i4 % (NT / 4));
    const int ch = (int)((i4 / (NT / 4)) % NC);
    const int b  = (int)(i4 / ((long)NC * (NT / 4)));
    const long base = (long)b * N3C * NT + (long)(2 * NC + ch) * NT;
    const int t0 = t4 * 4;

    const float4 cur = *(const float4*)(qkv + base + t0);
    const float prev = (t0 > 0)       ? qkv[base + t0 - 1] : 0.f;
    const float nxt  = (t0 + 4 < NT)  ? qkv[base + t0 + 4] : 0.f;
    const int wc = (2 * NC + ch) * 3;
    const float w0 = w[wc + 0], w1 = w[wc + 1], w2 = w[wc + 2];

    float o[4];
    o[0] = w0 * prev  + w1 * cur.x + w2 * cur.y;
    o[1] = w0 * cur.x + w1 * cur.y + w2 * cur.z;
    o[2] = w0 * cur.y + w1 * cur.z + w2 * cur.w;
    o[3] = w0 * cur.z + w1 * cur.w + w2 * nxt;

    const long oo = (long)b * NC * NT + (long)ch * NT + t0;
    uint2 hi, lo;
    split4(o, hi, lo);
    *(uint2*)(vh + oo) = hi;
    *(uint2*)(vl + oo) = lo;
}

// ---------------------------------------------------------------------------
// Row softmax over T, float4 loads, packed bf16 hi/lo stores
// ---------------------------------------------------------------------------
__global__ void softmax_split_kernel(const float* __restrict__ scores,
                                     __nv_bfloat16* __restrict__ ah,
                                     __nv_bfloat16* __restrict__ al)
{
    const long row = blockIdx.x;
    const float4* p4 = (const float4*)(scores + row * NT);
    const int tid  = threadIdx.x;
    const int lane = tid & 31;
    const int wid  = tid >> 5;
    __shared__ float red[8];

    float4 va = p4[tid], vb = p4[tid + 256];
    float vals[8] = {va.x, va.y, va.z, va.w, vb.x, vb.y, vb.z, vb.w};

    float m = -1e30f;
#pragma unroll
    for (int i = 0; i < 8; i++) m = fmaxf(m, vals[i]);
    m = warpMax(m);
    if (lane == 0) red[wid] = m;
    __syncthreads();
    if (wid == 0) {
        float v = (lane < 8) ? red[lane] : -1e30f;
        v = warpMax(v);
        if (lane == 0) red[0] = v;
    }
    __syncthreads();
    m = red[0];
    __syncthreads();

    float s = 0.f;
#pragma unroll
    for (int i = 0; i < 8; i++) { vals[i] = __expf(vals[i] - m); s += vals[i]; }
    s = warpSum(s);
    if (lane == 0) red[wid] = s;
    __syncthreads();
    if (wid == 0) {
        float v = (lane < 8) ? red[lane] : 0.f;
        v = warpSum(v);
        if (lane == 0) red[0] = v;
    }
    __syncthreads();
    const float inv = 1.f / red[0];

#pragma unroll
    for (int g = 0; g < 2; g++) {
        float v[4];
#pragma unroll
        for (int i = 0; i < 4; i++) v[i] = vals[g * 4 + i] * inv;
        uint2 hi, lo;
        split4(v, hi, lo);
        const long o = row * NT + (long)(tid + g * 256) * 4;
        *(uint2*)(ah + o) = hi;
        *(uint2*)(al + o) = lo;
    }
}

// ---------------------------------------------------------------------------
// Launch
// ---------------------------------------------------------------------------
extern "C" void kernel_launch(void* const* d_in, const int* in_sizes, int n_in,
                              void* d_out, int out_size)
{
    const float* x      = (const float*)d_in[0];
    const float* w_qkv  = (const float*)d_in[1];
    const float* w_dw   = (const float*)d_in[2];
    const float* w_proj = (const float*)d_in[3];
    float* out = (float*)d_out;

    cudaFuncSetAttribute(gemm_bf16x3<0>, cudaFuncAttributeMaxDynamicSharedMemorySize, GEMM_SMEM);
    cudaFuncSetAttribute(gemm_bf16x3<1>, cudaFuncAttributeMaxDynamicSharedMemorySize, GEMM_SMEM);
    cudaFuncSetAttribute(qk_fuse_kernel, cudaFuncAttributeMaxDynamicSharedMemorySize, QK_SMEM);

    float *qkv, *scores;
    cudaGetSymbolAddress((void**)&qkv,    g_qkv);
    cudaGetSymbolAddress((void**)&scores, g_scores);

    __nv_bfloat16 *wqh, *wql, *wph, *wpl, *xth, *xtl, *qth, *qtl, *kth, *ktl,
                  *vh, *vl, *ath, *atl, *oth, *otl;
    cudaGetSymbolAddress((void**)&wqh, g_wq_h);  cudaGetSymbolAddress((void**)&wql, g_wq_l);
    cudaGetSymbolAddress((void**)&wph, g_wp_h);  cudaGetSymbolAddress((void**)&wpl, g_wp_l);
    cudaGetSymbolAddress((void**)&xth, g_xT_h);  cudaGetSymbolAddress((void**)&xtl, g_xT_l);
    cudaGetSymbolAddress((void**)&qth, g_qT_h);  cudaGetSymbolAddress((void**)&qtl, g_qT_l);
    cudaGetSymbolAddress((void**)&kth, g_kT_h);  cudaGetSymbolAddress((void**)&ktl, g_kT_l);
    cudaGetSymbolAddress((void**)&vh,  g_v_h);   cudaGetSymbolAddress((void**)&vl,  g_v_l);
    cudaGetSymbolAddress((void**)&ath, g_at_h);  cudaGetSymbolAddress((void**)&atl, g_at_l);
    cudaGetSymbolAddress((void**)&oth, g_oT_h);  cudaGetSymbolAddress((void**)&otl, g_oT_l);

    // both weight splits in one launch
    {
        const long n1 = (long)N3C * NC, n2 = (long)NC * NC;
        split_weights<<<(unsigned)((n1 + n2 + 255) / 256), 256>>>(
            w_qkv, wqh, wql, n1, w_proj, wph, wpl, n2);
    }

    // xT split (transpose [C,T] -> [T,C])
    {
        dim3 grid(NT / 32, NC / 32, NB);
        tsplit_kernel<<<grid, 256>>>(x, xth, xtl);
    }

    // 1) qkv = W_qkv @ x : M=1536, N=2048, K=512 -> fp32
    {
        dim3 grid(NT / 128, N3C / 128, NB);
        gemm_bf16x3<0><<<grid, 256, GEMM_SMEM>>>(wqh, wql, xth, xtl, qkv, nullptr, nullptr,
            512, NT, 0L, (long)NT * NC, (long)N3C * NT);
    }

    // 2) fused dwconv + L2norm + transpose-split for q,k
    {
        dim3 grid(NT / 32, NB, 2);
        qk_fuse_kernel<<<grid, 256, QK_SMEM>>>(qkv, w_dw, qth, qtl, kth, ktl);
    }

    // 3) dwconv for v -> bf16 hi/lo
    {
        const long total4 = (long)NB * NC * (NT / 4);
        vdw_kernel<<<(unsigned)((total4 + 255) / 256), 256>>>(qkv, w_dw, vh, vl);
    }

    // 4) scores = qT @ kT^T : M=N=2048, K=512 -> fp32
    {
        dim3 grid(NT / 128, NT / 128, NB);
        gemm_bf16x3<0><<<grid, 256, GEMM_SMEM>>>(qth, qtl, kth, ktl, scores, nullptr, nullptr,
            512, NT, (long)NT * NC, (long)NT * NC, (long)NT * NT);
    }

    // 5) softmax + bf16 split
    softmax_split_kernel<<<NB * NT, 256>>>(scores, ath, atl);

    // 6) outT = attn @ v^T : M=2048, N=512, K=2048 -> bf16 hi/lo direct
    {
        dim3 grid(NC / 128, NT / 128, NB);
        gemm_bf16x3<1><<<grid, 256, GEMM_SMEM>>>(ath, atl, vh, vl, nullptr, oth, otl,
            2048, NC, (long)NT * NT, (long)NC * NT, (long)NT * NC);
    }

    // 7) final = W_proj @ outT^T : M=512, N=2048, K=512 -> fp32 d_out
    {
        dim3 grid(NT / 128, NC / 128, NB);
        gemm_bf16x3<0><<<grid, 256, GEMM_SMEM>>>(wph, wpl, oth, otl, out, nullptr, nullptr,
            512, NT, 0L, (long)NT * NC, (long)NC * NT);
    }
}